// round 7
// baseline (speedup 1.0000x reference)
#include <cuda_runtime.h>
#include <float.h>
#include <math.h>

// Problem constants (fixed by reference setup_inputs)
#define BB 8
#define SS 4096
#define CC 1024
#define HH 64
#define NS 128          // S splits for partial reduction
#define SROWS (SS/NS)   // 32 rows per partial chunk

// Scratch (no allocations allowed in kernel_launch)
__device__ float g_psum[BB*NS*CC];
__device__ float g_pmax[BB*NS*CC];
__device__ int   g_pcnt[BB*NS];
__device__ float g_a   [BB*CC];

// ---------------------------------------------------------------------------
// Kernel 1: partial masked sum/max over a 32-row chunk, full 1024 channels.
// Warp-ballot compaction of valid rows -> branch-free loop, 4 rows/iter.
// grid (NS, BB) = 1024 blocks, 256 threads.
// ---------------------------------------------------------------------------
__global__ void k_partial(const float* __restrict__ x,
                          const int*   __restrict__ mask) {
    const int ns = blockIdx.x;
    const int b  = blockIdx.y;
    const int c4 = threadIdx.x;              // float4 index 0..255

    __shared__ int srows[SROWS];
    __shared__ int snv;
    const int s0 = ns * SROWS;

    if (threadIdx.x < 32) {
        const int lane = threadIdx.x;
        const int m = mask[b * SS + s0 + lane];
        const unsigned bal = __ballot_sync(0xFFFFFFFFu, m != 0);
        if (m) srows[__popc(bal & ((1u << lane) - 1u))] = lane;
        if (lane == 0) {
            snv = __popc(bal);
            g_pcnt[b * NS + ns] = __popc(bal);
        }
    }
    __syncthreads();
    const int nv = snv;

    float4 sum = make_float4(0.f, 0.f, 0.f, 0.f);
    float4 mx  = make_float4(-FLT_MAX, -FLT_MAX, -FLT_MAX, -FLT_MAX);

    const float4* xp = reinterpret_cast<const float4*>(
        x + ((size_t)b * SS + s0) * CC) + c4;

    int i = 0;
    for (; i + 4 <= nv; i += 4) {
        const int r0 = srows[i];
        const int r1 = srows[i + 1];
        const int r2 = srows[i + 2];
        const int r3 = srows[i + 3];
        float4 v0 = xp[(size_t)r0 * (CC / 4)];
        float4 v1 = xp[(size_t)r1 * (CC / 4)];
        float4 v2 = xp[(size_t)r2 * (CC / 4)];
        float4 v3 = xp[(size_t)r3 * (CC / 4)];
        sum.x += v0.x; sum.y += v0.y; sum.z += v0.z; sum.w += v0.w;
        mx.x = fmaxf(mx.x, v0.x); mx.y = fmaxf(mx.y, v0.y);
        mx.z = fmaxf(mx.z, v0.z); mx.w = fmaxf(mx.w, v0.w);
        sum.x += v1.x; sum.y += v1.y; sum.z += v1.z; sum.w += v1.w;
        mx.x = fmaxf(mx.x, v1.x); mx.y = fmaxf(mx.y, v1.y);
        mx.z = fmaxf(mx.z, v1.z); mx.w = fmaxf(mx.w, v1.w);
        sum.x += v2.x; sum.y += v2.y; sum.z += v2.z; sum.w += v2.w;
        mx.x = fmaxf(mx.x, v2.x); mx.y = fmaxf(mx.y, v2.y);
        mx.z = fmaxf(mx.z, v2.z); mx.w = fmaxf(mx.w, v2.w);
        sum.x += v3.x; sum.y += v3.y; sum.z += v3.z; sum.w += v3.w;
        mx.x = fmaxf(mx.x, v3.x); mx.y = fmaxf(mx.y, v3.y);
        mx.z = fmaxf(mx.z, v3.z); mx.w = fmaxf(mx.w, v3.w);
    }
    for (; i < nv; i++) {
        const int r0 = srows[i];
        float4 v0 = xp[(size_t)r0 * (CC / 4)];
        sum.x += v0.x; sum.y += v0.y; sum.z += v0.z; sum.w += v0.w;
        mx.x = fmaxf(mx.x, v0.x); mx.y = fmaxf(mx.y, v0.y);
        mx.z = fmaxf(mx.z, v0.z); mx.w = fmaxf(mx.w, v0.w);
    }

    reinterpret_cast<float4*>(g_psum + (b * NS + ns) * CC)[c4] = sum;
    reinterpret_cast<float4*>(g_pmax + (b * NS + ns) * CC)[c4] = mx;
}

// ---------------------------------------------------------------------------
// Kernel 2 (fused): fold partials -> mean/max (parallel float4), then MLP.
// grid = BB, 1024 threads: phase 1 = 4 ns-slices x 256 float4 groups.
// ---------------------------------------------------------------------------
__global__ void __launch_bounds__(1024)
k_fused(const float* __restrict__ W0,     // [H, C]
        const float* __restrict__ W1) {   // [C, H]
    const int b = blockIdx.x;
    const int tid  = threadIdx.x;
    const int warp = tid >> 5;
    const int lane = tid & 31;

    __shared__ float4 s4sum[4][256];      // 16 KB
    __shared__ float4 s4max[4][256];      // 16 KB
    __shared__ float  smean[CC];          // 4 KB
    __shared__ float  smax [CC];          // 4 KB
    __shared__ float  hsum [HH];
    __shared__ float  scount;

    // ---- Phase 1: fold NS=128 partials, 4 slices of 32 each -------------
    {
        const int c4 = tid & 255;
        const int sl = tid >> 8;          // 0..3
        float4 sum = make_float4(0.f, 0.f, 0.f, 0.f);
        float4 mx  = make_float4(-FLT_MAX, -FLT_MAX, -FLT_MAX, -FLT_MAX);
        const float4* ps = reinterpret_cast<const float4*>(
            g_psum + (b * NS + sl * 32) * CC) + c4;
        const float4* pm = reinterpret_cast<const float4*>(
            g_pmax + (b * NS + sl * 32) * CC) + c4;
        #pragma unroll 8
        for (int k = 0; k < 32; k++) {
            float4 s = ps[(size_t)k * (CC / 4)];
            float4 m = pm[(size_t)k * (CC / 4)];
            sum.x += s.x; sum.y += s.y; sum.z += s.z; sum.w += s.w;
            mx.x = fmaxf(mx.x, m.x); mx.y = fmaxf(mx.y, m.y);
            mx.z = fmaxf(mx.z, m.z); mx.w = fmaxf(mx.w, m.w);
        }
        s4sum[sl][c4] = sum;
        s4max[sl][c4] = mx;

        // count reduction (warp 0): 128 ints
        if (warp == 0) {
            const int* pc = g_pcnt + b * NS;
            int c = pc[lane] + pc[lane + 32] + pc[lane + 64] + pc[lane + 96];
            #pragma unroll
            for (int off = 16; off > 0; off >>= 1)
                c += __shfl_xor_sync(0xFFFFFFFFu, c, off);
            if (lane == 0) scount = fmaxf((float)c, 1.0f);
        }
        __syncthreads();

        // fold 4 slices: threads 0..255
        if (tid < 256) {
            float4 a0 = s4sum[0][tid], a1 = s4sum[1][tid],
                   a2 = s4sum[2][tid], a3 = s4sum[3][tid];
            float4 m0 = s4max[0][tid], m1 = s4max[1][tid],
                   m2 = s4max[2][tid], m3 = s4max[3][tid];
            const float inv = 1.0f / scount;
            float4 S, M;
            S.x = (a0.x + a1.x + a2.x + a3.x) * inv;
            S.y = (a0.y + a1.y + a2.y + a3.y) * inv;
            S.z = (a0.z + a1.z + a2.z + a3.z) * inv;
            S.w = (a0.w + a1.w + a2.w + a3.w) * inv;
            M.x = fmaxf(fmaxf(m0.x, m1.x), fmaxf(m2.x, m3.x));
            M.y = fmaxf(fmaxf(m0.y, m1.y), fmaxf(m2.y, m3.y));
            M.z = fmaxf(fmaxf(m0.z, m1.z), fmaxf(m2.z, m3.z));
            M.w = fmaxf(fmaxf(m0.w, m1.w), fmaxf(m2.w, m3.w));
            reinterpret_cast<float4*>(smean)[tid] = S;
            reinterpret_cast<float4*>(smax )[tid] = M;
        }
        __syncthreads();
    }

    // ---- Phase 2: hidden layer (one warp per 2 hidden units) ------------
    #pragma unroll
    for (int jj = 0; jj < 2; jj++) {
        const int j = warp + jj * 32;
        const float* w = W0 + j * CC;
        float dm = 0.0f, dx = 0.0f;
        #pragma unroll 8
        for (int k = lane; k < CC; k += 32) {
            float wv = w[k];
            dm += wv * smean[k];
            dx += wv * smax[k];
        }
        #pragma unroll
        for (int off = 16; off > 0; off >>= 1) {
            dm += __shfl_xor_sync(0xFFFFFFFFu, dm, off);
            dx += __shfl_xor_sync(0xFFFFFFFFu, dx, off);
        }
        if (lane == 0)
            hsum[j] = fmaxf(dm, 0.0f) + fmaxf(dx, 0.0f);
    }
    __syncthreads();

    // ---- Phase 3: output layer + sigmoid (thread = channel) -------------
    {
        const float4* w1 = reinterpret_cast<const float4*>(W1 + tid * HH);
        float acc = 0.0f;
        #pragma unroll
        for (int j = 0; j < HH / 4; j++) {
            float4 w = w1[j];
            acc += w.x * hsum[j * 4 + 0] + w.y * hsum[j * 4 + 1]
                 + w.z * hsum[j * 4 + 2] + w.w * hsum[j * 4 + 3];
        }
        g_a[b * CC + tid] = 1.0f / (1.0f + expf(-acc));
    }
}

// ---------------------------------------------------------------------------
// Kernel 3: out[b,s,c] = x[b,s,c] * a[b,c]   (float4 streaming, .cs hints)
// grid ((S*C/4)/256, B)
// ---------------------------------------------------------------------------
__global__ void k_scale(const float* __restrict__ x,
                        float*       __restrict__ out) {
    const int b = blockIdx.y;
    const unsigned i = blockIdx.x * blockDim.x + threadIdx.x;  // float4 idx
    const unsigned c4 = i & (CC / 4 - 1);                       // 0..255

    const size_t gi = (size_t)b * (SS * CC / 4) + i;
    float4 v = __ldcs(reinterpret_cast<const float4*>(x) + gi);
    float4 a = reinterpret_cast<const float4*>(g_a + b * CC)[c4];
    v.x *= a.x; v.y *= a.y; v.z *= a.z; v.w *= a.w;
    __stcs(reinterpret_cast<float4*>(out) + gi, v);
}

// ---------------------------------------------------------------------------
extern "C" void kernel_launch(void* const* d_in, const int* in_sizes, int n_in,
                              void* d_out, int out_size) {
    const float* x    = (const float*)d_in[0];   // [B,S,C]
    const int*   mask = (const int*)  d_in[1];   // [B,S]
    const float* W0   = (const float*)d_in[2];   // [H,C]
    const float* W1   = (const float*)d_in[3];   // [C,H]
    float*       out  = (float*)d_out;           // [B,S,C]

    (void)in_sizes; (void)n_in; (void)out_size;

    {   dim3 grid(NS, BB);                  k_partial<<<grid, 256>>>(x, mask); }
    {   k_fused<<<BB, 1024>>>(W0, W1); }
    {   dim3 grid((SS * CC / 4) / 256, BB); k_scale<<<grid, 256>>>(x, out);    }
}